// round 1
// baseline (speedup 1.0000x reference)
#include <cuda_runtime.h>
#include <cstdint>

// Problem constants (fixed by the reference):
//   w : [512, 64] int indices in [0, 8192)   -> 32768 tokens
//   W : [8192, 8192] float32 (row-major, torch Linear weight [out, in])
//   b : [8192] float32
//   out[t, n] = W[n, w[t]] + b[n]   (i.e. column w[t] of W, plus bias)
// Strategy: transpose W into WT (coalesced smem transpose), then gather
// contiguous rows of WT with float4 + add bias. Everything coalesced.

#define N_LOC 8192
#define N_TOK 32768

// 256 MB scratch for W^T. __device__ globals are the sanctioned scratch
// mechanism (no allocations allowed in kernel_launch).
__device__ float g_WT[(size_t)N_LOC * N_LOC];

// 1 if the index tensor is int64 (8 bytes/elem), 0 if int32.
__device__ int g_idx_is64;

// ---------------------------------------------------------------------------
// Detect index dtype. If data is int64, the high 32-bit word of every element
// is 0 (values < 8192). If data is int32, the odd 32-bit words within the
// first 32768 words are real indices and are nonzero with overwhelming
// probability. OR-reduce odd words; nonzero => int32.
// ---------------------------------------------------------------------------
__global__ void detect_idx_dtype_kernel(const unsigned int* __restrict__ wraw) {
    __shared__ unsigned int acc_sh;
    if (threadIdx.x == 0) acc_sh = 0u;
    __syncthreads();
    unsigned int acc = 0u;
    // words 1,3,5,...,32767 (16384 words) — always within the buffer for
    // either dtype (int32: 32768 words total; int64: 65536 words total).
    for (int i = threadIdx.x; i < 16384; i += blockDim.x) {
        acc |= wraw[2 * i + 1];
    }
    // warp+block reduce via atomics on shared (tiny)
    atomicOr(&acc_sh, acc);
    __syncthreads();
    if (threadIdx.x == 0) {
        g_idx_is64 = (acc_sh == 0u) ? 1 : 0;
    }
}

// ---------------------------------------------------------------------------
// Tiled 32x32 shared-memory transpose: WT[c, n] = W[n, c].
// N divisible by 32, no bounds checks. Padding avoids bank conflicts.
// ---------------------------------------------------------------------------
__global__ void transpose_kernel(const float* __restrict__ in) {
    __shared__ float tile[32][33];
    int x = blockIdx.x * 32 + threadIdx.x;   // column in W
    int y = blockIdx.y * 32 + threadIdx.y;   // row in W
#pragma unroll
    for (int j = 0; j < 32; j += 8) {
        tile[threadIdx.y + j][threadIdx.x] = in[(size_t)(y + j) * N_LOC + x];
    }
    __syncthreads();
    int xo = blockIdx.y * 32 + threadIdx.x;  // column in WT (= row in W)
    int yo = blockIdx.x * 32 + threadIdx.y;  // row in WT (= column in W)
#pragma unroll
    for (int j = 0; j < 32; j += 8) {
        g_WT[(size_t)(yo + j) * N_LOC + xo] = tile[threadIdx.x][threadIdx.y + j];
    }
}

// ---------------------------------------------------------------------------
// Gather + bias: one block per token. Row of WT is 8192 floats = 2048 float4,
// 256 threads x 8 float4 each. Fully coalesced reads and writes.
// ---------------------------------------------------------------------------
__global__ void __launch_bounds__(256) gather_bias_kernel(
    const void* __restrict__ widx,
    const float* __restrict__ b,
    float* __restrict__ out)
{
    int t = blockIdx.x;
    long long idx;
    if (g_idx_is64) {
        idx = ((const long long*)widx)[t];
    } else {
        idx = (long long)((const int*)widx)[t];
    }

    const float4* __restrict__ src =
        (const float4*)(g_WT + (size_t)idx * N_LOC);
    const float4* __restrict__ bb = (const float4*)b;
    float4* __restrict__ dst = (float4*)(out + (size_t)t * N_LOC);

#pragma unroll
    for (int k = 0; k < 8; k++) {
        int i = threadIdx.x + k * 256;       // 0..2047
        float4 v  = __ldg(&src[i]);
        float4 bv = __ldg(&bb[i]);
        v.x += bv.x; v.y += bv.y; v.z += bv.z; v.w += bv.w;
        dst[i] = v;
    }
}

extern "C" void kernel_launch(void* const* d_in, const int* in_sizes, int n_in,
                              void* d_out, int out_size) {
    const void*  w_idx = d_in[0];                 // [32768] int32 or int64
    const float* W     = (const float*)d_in[1];   // [8192, 8192]
    const float* b     = (const float*)d_in[2];   // [8192]
    float*       out   = (float*)d_out;           // [32768, 8192]

    detect_idx_dtype_kernel<<<1, 256>>>((const unsigned int*)w_idx);

    dim3 tb(32, 8);
    dim3 tg(N_LOC / 32, N_LOC / 32);
    transpose_kernel<<<tg, tb>>>(W);

    gather_bias_kernel<<<N_TOK, 256>>>(w_idx, b, out);
}

// round 2
// speedup vs baseline: 1.6061x; 1.6061x over previous
#include <cuda_runtime.h>
#include <cstdint>

// out[t, :] = W[:, w[t]] + b   for 32768 tokens, W 8192x8192 fp32.
//
// Traffic-optimal plan:
//   1) prep_kernel (1 block): detect idx dtype (int32 vs int64), histogram
//      indices, exclusive scan, counting-sort tokens by index into g_pack.
//   2) scatter_kernel: grid (256 col-groups x 64 row-chunks). Each block
//      loads W[n0:n0+128, i0:i0+32] (coalesced 128B per row, each W line
//      read exactly ONCE chip-wide), transposes in smem, then for every
//      token whose index falls in this column group, writes
//      out[t, n0:n0+128] = column + bias with coalesced 128B stores.
// DRAM: 0.25 GiB read (W) + 1 GiB write (out) + noise  ~= the floor.

#define N_LOC 8192
#define N_TOK 32768
#define G 32                 // columns (indices) per group
#define R 128                // rows per chunk
#define NG (N_LOC / G)       // 256
#define NC (N_LOC / R)       // 64

__device__ int g_offset[N_LOC + 1];     // exclusive scan of index histogram
__device__ unsigned g_pack[N_TOK];      // tokens sorted by index: (i<<17)|t

// ---------------------------------------------------------------------------
// One-block prep: dtype detect + counting sort (all in shared memory).
// int64 detection: values < 8192, so every high word is 0; for int32 the odd
// words are real indices (nonzero with overwhelming probability).
// ---------------------------------------------------------------------------
__global__ void __launch_bounds__(1024) prep_kernel(const unsigned int* __restrict__ wraw) {
    __shared__ int sh_cnt[N_LOC];       // 32 KB histogram / offsets / cursors
    __shared__ unsigned sh_or;
    __shared__ int sh_warp[32];
    int tid = threadIdx.x;
    if (tid == 0) sh_or = 0u;
    for (int j = tid; j < N_LOC; j += 1024) sh_cnt[j] = 0;
    __syncthreads();

    unsigned acc = 0u;
    for (int i = tid; i < N_TOK / 2; i += 1024) acc |= wraw[2 * i + 1];
#pragma unroll
    for (int o = 16; o; o >>= 1) acc |= __shfl_xor_sync(~0u, acc, o);
    if ((tid & 31) == 0) atomicOr(&sh_or, acc);
    __syncthreads();
    const bool is64 = (sh_or == 0u);

    // shared-memory histogram
    for (int t = tid; t < N_TOK; t += 1024) {
        int i = is64 ? (int)((const long long*)wraw)[t]
                     : ((const int*)wraw)[t];
        atomicAdd(&sh_cnt[i], 1);
    }
    __syncthreads();

    // exclusive scan: each thread owns 8 consecutive bins
    int base = tid * 8;
    int v[8];
    int tot = 0;
#pragma unroll
    for (int m = 0; m < 8; m++) { v[m] = sh_cnt[base + m]; tot += v[m]; }

    int lane = tid & 31, wid = tid >> 5;
    int s = tot;
#pragma unroll
    for (int o = 1; o < 32; o <<= 1) {
        int x = __shfl_up_sync(~0u, s, o);
        if (lane >= o) s += x;
    }
    if (lane == 31) sh_warp[wid] = s;
    __syncthreads();
    if (wid == 0) {
        int t2 = sh_warp[lane];
        int s2 = t2;
#pragma unroll
        for (int o = 1; o < 32; o <<= 1) {
            int x = __shfl_up_sync(~0u, s2, o);
            if (lane >= o) s2 += x;
        }
        sh_warp[lane] = s2 - t2;   // exclusive warp prefix
    }
    __syncthreads();
    int run = sh_warp[wid] + (s - tot);  // block-exclusive prefix
#pragma unroll
    for (int m = 0; m < 8; m++) {
        g_offset[base + m] = run;
        sh_cnt[base + m] = run;          // becomes scatter cursor
        run += v[m];
    }
    if (tid == 1023) g_offset[N_LOC] = run;  // == N_TOK
    __syncthreads();

    // scatter tokens sorted by index (i:13 bits << 17 | t:15 bits)
    for (int t = tid; t < N_TOK; t += 1024) {
        int i = is64 ? (int)((const long long*)wraw)[t]
                     : ((const int*)wraw)[t];
        int pos = atomicAdd(&sh_cnt[i], 1);
        g_pack[pos] = ((unsigned)i << 17) | (unsigned)t;
    }
}

// ---------------------------------------------------------------------------
// Tile-transpose + broadcast-to-tokens.
// ---------------------------------------------------------------------------
__global__ void __launch_bounds__(256) scatter_kernel(
    const float* __restrict__ W,
    const float* __restrict__ bias,
    float* __restrict__ out)
{
    __shared__ float tile[G][R + 1];     // [col][row], 32x129 fp32 = 16.5 KB
    const int g     = blockIdx.x;        // column group
    const int chunk = blockIdx.y;        // row chunk
    const int i0 = g * G;
    const int n0 = chunk * R;
    const int tid = threadIdx.x;

    // Load W[n0:n0+R, i0:i0+G]: R rows x 128B, coalesced.
    // 1024 float4s total; thread does 4. Smem stores are bank-conflict-free
    // (per j: bank = (4q + r) mod 32, all distinct across the warp).
    const float4* __restrict__ Wv =
        (const float4*)(W + (size_t)n0 * N_LOC + i0);
#pragma unroll
    for (int k = 0; k < 4; k++) {
        int fid = tid + k * 256;         // 0..1023
        int r = fid >> 3;                // row 0..127
        int q = fid & 7;                 // float4 within row
        float4 v = __ldg(&Wv[(size_t)r * (N_LOC / 4) + q]);
        tile[4 * q + 0][r] = v.x;
        tile[4 * q + 1][r] = v.y;
        tile[4 * q + 2][r] = v.z;
        tile[4 * q + 3][r] = v.w;
    }

    const int lane = tid & 31, wid = tid >> 5;
    // lane covers out elements n0 + lane + 32k, k=0..3
    float bb[4];
#pragma unroll
    for (int k = 0; k < 4; k++) bb[k] = __ldg(&bias[n0 + lane + 32 * k]);
    __syncthreads();

    const int start = g_offset[i0];
    const int end   = g_offset[i0 + G];

    // each warp takes every 8th token in this group's sorted segment
    for (int j = start + wid; j < end; j += 8) {
        unsigned p = g_pack[j];          // broadcast load (same addr all lanes)
        int t = (int)(p & 0x1FFFFu);
        int c = (int)(p >> 17) - i0;
        float* __restrict__ dst = out + (size_t)t * N_LOC + n0;
#pragma unroll
        for (int k = 0; k < 4; k++) {
            // LDS conflict-free (fixed c, consecutive lanes); STG.32 x4,
            // each 128B fully coalesced -> 512B contiguous per token.
            dst[lane + 32 * k] = tile[c][lane + 32 * k] + bb[k];
        }
    }
}

extern "C" void kernel_launch(void* const* d_in, const int* in_sizes, int n_in,
                              void* d_out, int out_size) {
    const void*  w_idx = d_in[0];                 // [512,64] int32 or int64
    const float* W     = (const float*)d_in[1];   // [8192, 8192]
    const float* b     = (const float*)d_in[2];   // [8192]
    float*       out   = (float*)d_out;           // [32768, 8192]

    prep_kernel<<<1, 1024>>>((const unsigned int*)w_idx);

    dim3 grid(NG, NC);
    scatter_kernel<<<grid, 256>>>(W, b, out);
}